// round 16
// baseline (speedup 1.0000x reference)
#include <cuda_runtime.h>
#include <cuda_fp16.h>
#include <cstdint>
#include <cstddef>

// ---------------------------------------------------------------------------
// SupervisedTEMTransition on GB300 (sm_103a), round 10.
//   cls GEMM made persistent: 2xSM CTAs, each loops ~14 tiles with the
//   cp.async ring continuing across tile boundaries (fill paid once per CTA,
//   epilogue overlapped, no wave transitions). fp16 m16n8k16 path from R9.
//   trans/conv/bin unchanged.
// ---------------------------------------------------------------------------

#define BATCH_MAX   16384
#define G_TOTAL     768
#define NUM_STATES  4096
#define N_ACTIONS   4

__device__ int    d_perm[BATCH_MAX];
__device__ int    d_off[N_ACTIONS + 1];
__device__ __half d_gh[(size_t)BATCH_MAX * G_TOTAL];     // fp16 g_next (cls A)
__device__ __half d_wh[(size_t)NUM_STATES * G_TOTAL];    // fp16 W
__device__ __half d_eh[(size_t)NUM_STATES * G_TOTAL];    // fp16 emb
__device__ __half d_dh[655360];                          // fp16 D banks

__device__ __forceinline__ uint32_t smem_u32(const void* p) {
    uint32_t a;
    asm("{ .reg .u64 t; cvta.to.shared.u64 t, %1; cvt.u32.u64 %0, t; }"
        : "=r"(a) : "l"(p));
    return a;
}

__device__ __forceinline__ void cp16(uint32_t saddr, const void* g) {
    asm volatile("cp.async.cg.shared.global [%0], [%1], 16;"
                 :: "r"(saddr), "l"(g) : "memory");
}

__device__ __forceinline__ void ldsm4(uint32_t addr, uint32_t* r) {
    asm volatile("ldmatrix.sync.aligned.m8n8.x4.shared.b16 {%0,%1,%2,%3}, [%4];"
                 : "=r"(r[0]), "=r"(r[1]), "=r"(r[2]), "=r"(r[3]) : "r"(addr));
}

__device__ __forceinline__ void ldsm2(uint32_t addr, uint32_t* r) {
    asm volatile("ldmatrix.sync.aligned.m8n8.x2.shared.b16 {%0,%1}, [%2];"
                 : "=r"(r[0]), "=r"(r[1]) : "r"(addr));
}

#define MMA_F16(acc, a, b)                                                     \
    asm volatile(                                                              \
        "mma.sync.aligned.m16n8k16.row.col.f32.f16.f16.f32 "                   \
        "{%0,%1,%2,%3}, {%4,%5,%6,%7}, {%8,%9}, {%0,%1,%2,%3};"                \
        : "+f"((acc)[0]), "+f"((acc)[1]), "+f"((acc)[2]), "+f"((acc)[3])       \
        : "r"((a)[0]), "r"((a)[1]), "r"((a)[2]), "r"((a)[3]),                  \
          "r"((b)[0]), "r"((b)[1]))

// ---------------------------------------------------------------------------
// Kernel 0: merged fp32 -> fp16 conversion (emb, W, D0..D3). 8 elems/thread.
// ---------------------------------------------------------------------------
#define CONV_BLOCKS 3392

__global__ __launch_bounds__(256)
void conv_all_kernel(const float* __restrict__ emb, const float* __restrict__ W,
                     const float* __restrict__ D0, const float* __restrict__ D1,
                     const float* __restrict__ D2, const float* __restrict__ D3,
                     __half* __restrict__ he, __half* __restrict__ hw,
                     __half* __restrict__ hd)
{
    int blk = blockIdx.x;
    const float* src;
    __half* dst;
    int base;
    if (blk < 1536)      { src = emb; dst = he;          base = blk; }
    else if (blk < 3072) { src = W;   dst = hw;          base = blk - 1536; }
    else if (blk < 3200) { src = D0;  dst = hd;          base = blk - 3072; }
    else if (blk < 3328) { src = D1;  dst = hd + 262144; base = blk - 3200; }
    else if (blk < 3360) { src = D2;  dst = hd + 524288; base = blk - 3328; }
    else                 { src = D3;  dst = hd + 589824; base = blk - 3360; }

    int i = (base * 256 + threadIdx.x) * 8;
    float4 v0 = *(const float4*)(src + i);
    float4 v1 = *(const float4*)(src + i + 4);
    __half2 h0 = __floats2half2_rn(v0.x, v0.y);
    __half2 h1 = __floats2half2_rn(v0.z, v0.w);
    __half2 h2 = __floats2half2_rn(v1.x, v1.y);
    __half2 h3 = __floats2half2_rn(v1.z, v1.w);
    uint4 o;
    o.x = *(uint32_t*)&h0; o.y = *(uint32_t*)&h1;
    o.z = *(uint32_t*)&h2; o.w = *(uint32_t*)&h3;
    *(uint4*)(dst + i) = o;
}

// ---------------------------------------------------------------------------
// Kernel 1: bin rows by action (warp-aggregated atomics)
// ---------------------------------------------------------------------------
__global__ void bin_kernel(const int* __restrict__ act, int B) {
    __shared__ int cnt[N_ACTIONS];
    __shared__ int base[N_ACTIONS];
    int t = threadIdx.x;
    int lane = t & 31;
    if (t < N_ACTIONS) cnt[t] = 0;
    __syncthreads();
    for (int b = t; b < B; b += blockDim.x) {
        int a = act[b];
        #pragma unroll
        for (int aa = 0; aa < N_ACTIONS; aa++) {
            unsigned m = __ballot_sync(0xffffffffu, a == aa);
            if (m && lane == (__ffs(m) - 1))
                atomicAdd(&cnt[aa], __popc(m));
        }
    }
    __syncthreads();
    if (t == 0) {
        int s = 0;
        for (int a = 0; a < N_ACTIONS; a++) { base[a] = s; d_off[a] = s; s += cnt[a]; }
        d_off[N_ACTIONS] = s;
    }
    __syncthreads();
    if (t < N_ACTIONS) cnt[t] = 0;
    __syncthreads();
    for (int b = t; b < B; b += blockDim.x) {
        int a = act[b];
        int mypos = 0;
        #pragma unroll
        for (int aa = 0; aa < N_ACTIONS; aa++) {
            unsigned m = __ballot_sync(0xffffffffu, a == aa);
            if (m) {
                int leader = __ffs(m) - 1;
                int bw = 0;
                if (lane == leader) bw = atomicAdd(&cnt[aa], __popc(m));
                bw = __shfl_sync(0xffffffffu, bw, leader);
                if (a == aa) mypos = bw + __popc(m & ((1u << lane) - 1u));
            }
        }
        d_perm[base[a] + mypos] = b;
    }
}

// ---------------------------------------------------------------------------
// GEMM geometry: K-chunk = 64 halves, smem row stride KP = 72 halves.
// Stage = 256 rows x 144 B = 36864 B; 3 stages = 110592 B; 2 CTAs/SM.
// ---------------------------------------------------------------------------
#define KP           72
#define A_HALFS      (128 * KP)
#define STG_HALFS    (2 * 128 * KP)
#define STG_BYTES    (STG_HALFS * 2)
#define STAGES       3
#define DYN_SMEM_B   (STAGES * STG_BYTES)

extern __shared__ __half dyn_sm[];

// ---------------------------------------------------------------------------
// Kernel 2: merged routed transition, fp16 mma (unchanged from R9).
// ---------------------------------------------------------------------------
__global__ __launch_bounds__(256, 2)
void trans_mma_kernel(const __half* __restrict__ eh,
                      const float*  __restrict__ embx,
                      const int*    __restrict__ state,
                      const __half* __restrict__ dh,
                      __half* __restrict__ gdst,
                      float*  __restrict__ gout)
{
    const int a = blockIdx.z >> 2;
    const int f = blockIdx.z & 3;
    const int nf   = (f < 2) ? 256 : 128;
    const int moff = (f == 0) ? 0 : (f == 1) ? 256 : (f == 2) ? 512 : 640;
    const int doff = (f == 0) ? 0 : (f == 1) ? 262144 : (f == 2) ? 524288 : 589824;

    const int n0 = blockIdx.x * 128;
    if (n0 >= nf) return;
    const int r0 = blockIdx.y * 128;
    const int start = d_off[a];
    const int cnt   = d_off[a + 1] - start;
    if (r0 >= cnt) return;

    const int nk = nf / 64;
    const __half* Da = dh + doff + (size_t)a * nf * nf;
    const int tid = threadIdx.x;

    __shared__ int srow[128];
    __shared__ int sb[128];
    if (tid < 128) {
        int rr = r0 + tid;
        if (rr < cnt) {
            int bidx = d_perm[start + rr];
            sb[tid] = bidx;
            srow[tid] = state[bidx] * G_TOTAL;
        } else {
            sb[tid] = -1;
            srow[tid] = 0;
        }
    }
    __syncthreads();

    const __half* pa[4];
    const __half* pb[4];
    uint32_t sa[4], sbo[4];
    #pragma unroll
    for (int i = 0; i < 4; i++) {
        int u = tid + i * 256;
        int r = u >> 3, c = u & 7;
        pa[i] = eh + srow[r] + moff + c * 8;
        pb[i] = Da + (size_t)(n0 + r) * nf + c * 8;
        sa[i]  = (r * KP + c * 8) * 2;
        sbo[i] = (A_HALFS + r * KP + c * 8) * 2;
    }

    const uint32_t sbase = smem_u32(dyn_sm);

    #define T_ISSUE(c)                                                         \
        do {                                                                   \
            uint32_t _st = sbase + ((c) % STAGES) * STG_BYTES;                 \
            _Pragma("unroll")                                                  \
            for (int i = 0; i < 4; i++) cp16(_st + sa[i],  pa[i] + (c) * 64);  \
            _Pragma("unroll")                                                  \
            for (int i = 0; i < 4; i++) cp16(_st + sbo[i], pb[i] + (c) * 64);  \
            asm volatile("cp.async.commit_group;" ::: "memory");               \
        } while (0)

    T_ISSUE(0);
    T_ISSUE(1);

    const int lane = tid & 31;
    const int wid  = tid >> 5;
    const int g    = lane >> 2;
    const int tg   = lane & 3;
    const int wm   = (wid >> 2) * 64;
    const int wn   = (wid & 3) * 32;

    const uint32_t aoff =
        ((wm + (lane & 7) + ((lane >> 3) & 1) * 8) * KP) * 2 + (lane >> 4) * 16;
    const uint32_t boff =
        A_HALFS * 2 + ((wn + (lane & 7)) * KP) * 2 + ((lane >> 3) & 1) * 16;

    float acc[4][4][4] = {};

    for (int c = 0; c < nk; c++) {
        if (c < nk - 1)
            asm volatile("cp.async.wait_group 1;" ::: "memory");
        else
            asm volatile("cp.async.wait_group 0;" ::: "memory");
        __syncthreads();

        if (c + 2 < nk) T_ISSUE(c + 2);

        const uint32_t st = sbase + (c % STAGES) * STG_BYTES;

        #pragma unroll
        for (int ks = 0; ks < 4; ks++) {
            uint32_t af[4][4];
            #pragma unroll
            for (int mt = 0; mt < 4; mt++)
                ldsm4(st + aoff + mt * (16 * KP * 2) + ks * 32, af[mt]);
            uint32_t bf[4][2];
            #pragma unroll
            for (int nt = 0; nt < 4; nt++)
                ldsm2(st + boff + nt * (8 * KP * 2) + ks * 32, bf[nt]);
            #pragma unroll
            for (int mt = 0; mt < 4; mt++)
                #pragma unroll
                for (int nt = 0; nt < 4; nt++)
                    MMA_F16(acc[mt][nt], af[mt], bf[nt]);
        }
    }
    #undef T_ISSUE

    #pragma unroll
    for (int mt = 0; mt < 4; mt++) {
        #pragma unroll
        for (int half = 0; half < 2; half++) {
            int rr = wm + mt * 16 + g + half * 8;
            int bidx = sb[rr];
            if (bidx < 0) continue;
            int sr = srow[rr];
            #pragma unroll
            for (int nt = 0; nt < 4; nt++) {
                int col = moff + n0 + wn + nt * 8 + tg * 2;
                float2 gv = *(const float2*)(embx + sr + col);
                float v0 = gv.x + acc[mt][nt][half * 2 + 0];
                float v1 = gv.y + acc[mt][nt][half * 2 + 1];
                v0 = fminf(fmaxf(v0, -1.0f), 1.0f);
                v1 = fminf(fmaxf(v1, -1.0f), 1.0f);
                size_t ob = (size_t)bidx * G_TOTAL + col;
                *(__half2*)(gdst + ob) = __floats2half2_rn(v0, v1);
                if (gout)
                    *(float2*)(gout + ob) = make_float2(v0, v1);
            }
        }
    }
}

// ---------------------------------------------------------------------------
// Kernel 3: PERSISTENT fp16 classifier GEMM.
//   grid = 2 x #SMs. Each CTA loops over tiles (stride grid); the 3-stage
//   cp.async ring runs continuously across tile boundaries. 12 K-chunks of 64
//   per tile; tile t -> m0 = (t/32)*128, n0 = (t%32)*128.
// ---------------------------------------------------------------------------
#define NCHUNK   12
#define NTILES   ((BATCH_MAX / 128) * (NUM_STATES / 128))   // 4096

__global__ __launch_bounds__(256, 2)
void cls_mma_kernel(const __half* __restrict__ A,
                    const __half* __restrict__ W,
                    const float*  __restrict__ bias,
                    float* __restrict__ C)
{
    const int tid = threadIdx.x;
    const int bid = blockIdx.x;
    const int G   = gridDim.x;

    const int lane = tid & 31;
    const int wid  = tid >> 5;
    const int g    = lane >> 2;
    const int tg   = lane & 3;
    const int wm   = (wid >> 2) * 64;
    const int wn   = (wid & 3) * 32;

    const int lrow = tid >> 3;
    const int lcol = tid & 7;

    const uint32_t sbase = smem_u32(dyn_sm);
    const uint32_t sA0 = (lrow * KP + lcol * 8) * 2;
    const uint32_t sB0 = (A_HALFS + lrow * KP + lcol * 8) * 2;

    const uint32_t aoff =
        ((wm + (lane & 7) + ((lane >> 3) & 1) * 8) * KP) * 2 + (lane >> 4) * 16;
    const uint32_t boff =
        A_HALFS * 2 + ((wn + (lane & 7)) * KP) * 2 + ((lane >> 3) & 1) * 16;

    const int ntile = (bid < NTILES) ? ((NTILES - 1 - bid) / G + 1) : 0;
    const int P = ntile * NCHUNK;
    if (P == 0) return;

    // issue global chunk i (tile bid + (i/12)*G, chunk i%12)
    #define ISSUE(i)                                                           \
        do {                                                                   \
            int _ti = (i) / NCHUNK;                                            \
            int _ci = (i) - _ti * NCHUNK;                                      \
            int _tt = bid + _ti * G;                                           \
            int _m0 = (_tt >> 5) * 128;                                        \
            int _n0 = (_tt & 31) * 128;                                        \
            const __half* _gA = A + (size_t)(_m0 + lrow) * G_TOTAL             \
                                  + lcol * 8 + _ci * 64;                       \
            const __half* _gB = W + (size_t)(_n0 + lrow) * G_TOTAL             \
                                  + lcol * 8 + _ci * 64;                       \
            uint32_t _st = sbase + ((i) % STAGES) * STG_BYTES;                 \
            _Pragma("unroll")                                                  \
            for (int k4 = 0; k4 < 4; k4++)                                     \
                cp16(_st + sA0 + k4 * (32 * KP * 2),                           \
                     _gA + (size_t)k4 * 32 * G_TOTAL);                         \
            _Pragma("unroll")                                                  \
            for (int k4 = 0; k4 < 4; k4++)                                     \
                cp16(_st + sB0 + k4 * (32 * KP * 2),                           \
                     _gB + (size_t)k4 * 32 * G_TOTAL);                         \
            asm volatile("cp.async.commit_group;" ::: "memory");               \
        } while (0)

    ISSUE(0);
    ISSUE(1);
    int ic = 2;

    float acc[4][4][4] = {};

    for (int p = 0; p < P; p++) {
        if (p < P - 1)
            asm volatile("cp.async.wait_group 1;" ::: "memory");
        else
            asm volatile("cp.async.wait_group 0;" ::: "memory");
        __syncthreads();

        if (ic < P) { ISSUE(ic); ic++; }

        const uint32_t st = sbase + (p % STAGES) * STG_BYTES;

        #pragma unroll
        for (int kk = 0; kk < 4; kk++) {
            const int ks = (kk + wid) & 3;       // per-warp stagger
            uint32_t a[4][4];
            #pragma unroll
            for (int mt = 0; mt < 4; mt++)
                ldsm4(st + aoff + mt * (16 * KP * 2) + ks * 32, a[mt]);
            uint32_t b[4][2];
            #pragma unroll
            for (int nt = 0; nt < 4; nt++)
                ldsm2(st + boff + nt * (8 * KP * 2) + ks * 32, b[nt]);
            #pragma unroll
            for (int mt = 0; mt < 4; mt++)
                #pragma unroll
                for (int nt = 0; nt < 4; nt++)
                    MMA_F16(acc[mt][nt], a[mt], b[nt]);
        }

        // tile boundary: epilogue + acc reset (overlaps next tile's ring)
        if (p % NCHUNK == NCHUNK - 1) {
            int tt = bid + (p / NCHUNK) * G;
            int m0 = (tt >> 5) * 128;
            int n0 = (tt & 31) * 128;
            #pragma unroll
            for (int mt = 0; mt < 4; mt++) {
                int r_lo = m0 + wm + mt * 16 + g;
                float* C0 = C + (size_t)r_lo * NUM_STATES + n0;
                float* C1 = C + (size_t)(r_lo + 8) * NUM_STATES + n0;
                #pragma unroll
                for (int nt = 0; nt < 4; nt++) {
                    int nc = wn + nt * 8 + tg * 2;
                    float b0 = __ldg(bias + n0 + nc);
                    float b1 = __ldg(bias + n0 + nc + 1);
                    *(float2*)(C0 + nc) =
                        make_float2(acc[mt][nt][0] + b0, acc[mt][nt][1] + b1);
                    *(float2*)(C1 + nc) =
                        make_float2(acc[mt][nt][2] + b0, acc[mt][nt][3] + b1);
                    acc[mt][nt][0] = 0.f; acc[mt][nt][1] = 0.f;
                    acc[mt][nt][2] = 0.f; acc[mt][nt][3] = 0.f;
                }
            }
        }
    }
    #undef ISSUE
}

// ---------------------------------------------------------------------------
// Launch
// ---------------------------------------------------------------------------
extern "C" void kernel_launch(void* const* d_in, const int* in_sizes, int n_in,
                              void* d_out, int out_size)
{
    const int*   state = (const int*)d_in[0];
    const int*   act   = (const int*)d_in[1];
    const float* emb   = (const float*)d_in[2];

    const float *D0, *D1, *D2, *D3, *W, *bias;
    if (in_sizes[3] == NUM_STATES * G_TOTAL) {
        W  = (const float*)d_in[3];
        bias = (const float*)d_in[4];
        D0 = (const float*)d_in[5];
        D1 = (const float*)d_in[6];
        D2 = (const float*)d_in[7];
        D3 = (const float*)d_in[8];
    } else {
        D0 = (const float*)d_in[3];
        D1 = (const float*)d_in[4];
        D2 = (const float*)d_in[5];
        D3 = (const float*)d_in[6];
        W  = (const float*)d_in[7];
        bias = (const float*)d_in[8];
    }

    const int B = in_sizes[0];
    float* out = (float*)d_out;

    float* logits = out;
    float* gout = nullptr;
    if ((size_t)out_size >= (size_t)B * (NUM_STATES + G_TOTAL))
        gout = out + (size_t)B * NUM_STATES;

    __half *gh, *wh, *eh, *dh;
    cudaGetSymbolAddress((void**)&gh, d_gh);
    cudaGetSymbolAddress((void**)&wh, d_wh);
    cudaGetSymbolAddress((void**)&eh, d_eh);
    cudaGetSymbolAddress((void**)&dh, d_dh);

    cudaFuncSetAttribute(cls_mma_kernel,
                         cudaFuncAttributeMaxDynamicSharedMemorySize, DYN_SMEM_B);
    cudaFuncSetAttribute(trans_mma_kernel,
                         cudaFuncAttributeMaxDynamicSharedMemorySize, DYN_SMEM_B);

    int nsm = 148;
    cudaDeviceGetAttribute(&nsm, cudaDevAttrMultiProcessorCount, 0);

    // 0) fp32 -> fp16 conversion (single launch)
    conv_all_kernel<<<CONV_BLOCKS, 256>>>(emb, W, D0, D1, D2, D3, eh, wh, dh);

    // 1) bin rows by action
    bin_kernel<<<1, 1024>>>(act, B);

    // 2) merged routed transition (fp16 tensor cores)
    {
        dim3 grid(2, (B + 127) / 128, 16);
        trans_mma_kernel<<<grid, 256, DYN_SMEM_B>>>(eh, emb, state, dh, gh, gout);
    }

    // 3) persistent fp16 classifier GEMM
    cls_mma_kernel<<<2 * nsm, 256, DYN_SMEM_B>>>(gh, wh, bias, logits);
}